// round 16
// baseline (speedup 1.0000x reference)
#include <cuda_runtime.h>
#include <cuda_bf16.h>
#include <math.h>
#include <stdint.h>

// Problem dims (fixed by the dataset)
#define SS 128      // sequence length
#define BB 64       // batch
#define HH 1024     // hidden = embedding dim
#define VV 10000    // vocab
#define MM (SS*BB)  // 8192 rows for the batched GEMMs
#define BH (BB*HH)  // 65536
#define GW (BH/2)   // uint32 words per timestep in the fragment slab
#define NPAD 10240  // vocab padded to 128-multiple for tensor tiles
#define GRIDB 64    // scan grid (64 j-tiles of 16)

// ---------------- device scratch (no allocations allowed) ----------------
__device__ __align__(16) float g_pre0[MM * HH];          // drive layer 0, [t][b][j]
__device__ __align__(16) __nv_bfloat16 g_S0hi[(SS+1) * BH];
__device__ __align__(16) __nv_bfloat16 g_S0lo[(SS+1) * BH];
__device__ __align__(16) __nv_bfloat16 g_S1hi[(SS+1) * BH];
__device__ __align__(16) __nv_bfloat16 g_S1lo[(SS+1) * BH];
// Fragment-layout hidden slabs (scan B operand); see R11 mapping comment.
__device__ __align__(16) uint32_t g_G0hi[(SS+1) * GW];
__device__ __align__(16) uint32_t g_G0lo[(SS+1) * GW];
__device__ __align__(16) uint32_t g_G1hi[(SS+1) * GW];
__device__ __align__(16) uint32_t g_G1lo[(SS+1) * GW];
__device__ __align__(16) __nv_bfloat16 g_Ahi[MM * HH];   // gathered emb (hi)
__device__ __align__(16) __nv_bfloat16 g_Alo[MM * HH];   // gathered emb (lo)
__device__ __align__(16) __nv_bfloat16 g_Bhi[NPAD * HH]; // weight operand (hi)
__device__ __align__(16) __nv_bfloat16 g_Blo[NPAD * HH]; // weight operand (lo)
__device__ __align__(16) float g_bias1c[HH];             // b_ih1 + b_hh1
__device__ unsigned g_arrive;                            // grid barrier: arrivals
__device__ unsigned g_release;                           // grid barrier: generation

// ---------------- generic helpers ----------------
__device__ __forceinline__ unsigned ldcg_u(const unsigned* p) {
    unsigned v; asm volatile("ld.global.cg.u32 %0, [%1];" : "=r"(v) : "l"(p)); return v;
}
__device__ __forceinline__ unsigned smem_u32(const void* p) {
    unsigned a;
    asm("{ .reg .u64 t; cvta.to.shared.u64 t, %1; cvt.u32.u64 %0, t; }" : "=r"(a) : "l"(p));
    return a;
}
__device__ __forceinline__ void cp_async16(unsigned dst, const void* src) {
    asm volatile("cp.async.cg.shared.global [%0], [%1], 16;" :: "r"(dst), "l"(src));
}
__device__ __forceinline__ void cp_commit() {
    asm volatile("cp.async.commit_group;");
}
template<int N>
__device__ __forceinline__ void cp_wait() {
    asm volatile("cp.async.wait_group %0;" :: "n"(N));
}

// grid barrier over NB resident blocks
__device__ __forceinline__ void grid_barrier(unsigned want, unsigned NB) {
    __syncthreads();
    if (threadIdx.x == 0) {
        __threadfence();
        unsigned prev = atomicAdd(&g_arrive, 1u);
        if (prev == want * NB - 1u) {
            atomicExch(&g_release, want);
        }
        while (ldcg_u(&g_release) < want) { __nanosleep(32); }
    }
    __syncthreads();
}

// ---------------- split-bf16 helpers ----------------
__device__ __forceinline__ uint32_t pack_bf2(float a, float b) {
    __nv_bfloat162 t2;
    t2.x = __float2bfloat16(a);
    t2.y = __float2bfloat16(b);
    return *(uint32_t*)&t2;
}
__device__ __forceinline__ void split4_store(float4 v,
    __nv_bfloat16* hi, __nv_bfloat16* lo, size_t off)
{
    float vv[4] = {v.x, v.y, v.z, v.w};
    uint32_t ph[2], pl[2];
    #pragma unroll
    for (int e = 0; e < 2; e++) {
        __nv_bfloat16 h0 = __float2bfloat16(vv[e*2+0]);
        __nv_bfloat16 h1 = __float2bfloat16(vv[e*2+1]);
        __nv_bfloat16 l0 = __float2bfloat16(vv[e*2+0] - __bfloat162float(h0));
        __nv_bfloat16 l1 = __float2bfloat16(vv[e*2+1] - __bfloat162float(h1));
        __nv_bfloat162 hh; hh.x = h0; hh.y = h1; ph[e] = *(uint32_t*)&hh;
        __nv_bfloat162 ll; ll.x = l0; ll.y = l1; pl[e] = *(uint32_t*)&ll;
    }
    *(uint2*)(hi + off) = make_uint2(ph[0], ph[1]);
    *(uint2*)(lo + off) = make_uint2(pl[0], pl[1]);
}

// weights [Nrows][K] -> hi/lo, zero-padded rows up to grid coverage
__global__ void __launch_bounds__(256) conv_w(
    const float* __restrict__ W, int Nrows,
    __nv_bfloat16* __restrict__ hi, __nv_bfloat16* __restrict__ lo)
{
    const int idx = blockIdx.x * 256 + threadIdx.x;
    const int row = idx >> 8;
    const int c4  = (idx & 255) * 4;
    float4 v = make_float4(0.f, 0.f, 0.f, 0.f);
    if (row < Nrows) v = *(const float4*)&W[(size_t)row * HH + c4];
    split4_store(v, hi, lo, (size_t)row * HH + c4);
}

// gathered, scaled embedding -> hi/lo A slab [m][K]
__global__ void __launch_bounds__(256) conv_gather(
    const int* __restrict__ gidx, const float* __restrict__ emb,
    __nv_bfloat16* __restrict__ hi, __nv_bfloat16* __restrict__ lo)
{
    const int idx = blockIdx.x * 256 + threadIdx.x;
    const int m  = idx >> 8;
    const int c4 = (idx & 255) * 4;
    float4 v = *(const float4*)&emb[(size_t)gidx[m] * HH + c4];
    v.x *= 32.f; v.y *= 32.f; v.z *= 32.f; v.w *= 32.f;
    split4_store(v, hi, lo, (size_t)m * HH + c4);
}

// initial hidden [l][b][k] fp32 -> G slabs t=0 (fragment layout, hi/lo)
__global__ void __launch_bounds__(256) init_hid(const float* __restrict__ hidden)
{
    const int i = blockIdx.x * 256 + threadIdx.x;   // grid covers 2*BH/4
    const int l = i >= (BH / 4);
    const int r = i - l * (BH / 4);
    const int b = r >> 8, c4 = (r & 255) * 4;       // 4 consecutive k's
    float4 v = *(const float4*)&hidden[(size_t)l * BH + (size_t)b * HH + c4];

    const uint32_t p0h = pack_bf2(v.x, v.y);
    const uint32_t p1h = pack_bf2(v.z, v.w);
    const float rx = v.x - __bfloat162float(__float2bfloat16(v.x));
    const float ry = v.y - __bfloat162float(__float2bfloat16(v.y));
    const float rz = v.z - __bfloat162float(__float2bfloat16(v.z));
    const float rw = v.w - __bfloat162float(__float2bfloat16(v.w));
    const uint32_t p0l = pack_bf2(rx, ry);
    const uint32_t p1l = pack_bf2(rz, rw);

    const int ks = c4 >> 4, k16 = c4 & 15;
    const int g = b >> 4, n16 = b & 15;
    const int w = 2 * (n16 >= 8 ? 1 : 0) + (k16 >= 8 ? 1 : 0);
    const int lane = (n16 & 7) * 4 + ((k16 & 7) >> 1);
    const int off0 = ((ks * 4 + g) * 32 + lane) * 4 + w;

    uint32_t* GH = l ? g_G1hi : g_G0hi;
    uint32_t* GL = l ? g_G1lo : g_G0lo;
    GH[off0] = p0h; GH[off0 + 4] = p1h;
    GL[off0] = p0l; GL[off0 + 4] = p1l;
}

// ---------------- mma.sync bf16 split GEMM (exact R13: 3-stage BK32, occ=2) --
#define BKC   32
#define TSTR  40
#define NCHK  96
#define HG_BUF   (128 * TSTR)                 // bf16 per stage per operand
#define HG_SMEM  (3 * HG_BUF * 2 * 2)         // 61440 bytes

__device__ __forceinline__ void ldm_x4(uint32_t* r, uint32_t addr) {
    asm volatile("ldmatrix.sync.aligned.m8n8.x4.shared.b16 {%0,%1,%2,%3}, [%4];"
                 : "=r"(r[0]), "=r"(r[1]), "=r"(r[2]), "=r"(r[3]) : "r"(addr));
}
__device__ __forceinline__ void mma16816(float* c, const uint32_t* a, const uint32_t* b) {
    asm volatile(
        "mma.sync.aligned.m16n8k16.row.col.f32.bf16.bf16.f32 "
        "{%0,%1,%2,%3}, {%4,%5,%6,%7}, {%8,%9}, {%0,%1,%2,%3};"
        : "+f"(c[0]), "+f"(c[1]), "+f"(c[2]), "+f"(c[3])
        : "r"(a[0]), "r"(a[1]), "r"(a[2]), "r"(a[3]), "r"(b[0]), "r"(b[1]));
}

__global__ void __launch_bounds__(256, 2) hmma_gemm(
    const __nv_bfloat16* __restrict__ Ahi, const __nv_bfloat16* __restrict__ Alo,
    const __nv_bfloat16* __restrict__ Bhi, const __nv_bfloat16* __restrict__ Blo,
    const float* __restrict__ bias, float* __restrict__ C, int ldc, int Nvalid)
{
    extern __shared__ __nv_bfloat16 hsm[];
    __nv_bfloat16* As = hsm;                 // [3][HG_BUF]
    __nv_bfloat16* Bs = hsm + 3 * HG_BUF;    // [3][HG_BUF]

    const int tid  = threadIdx.x;
    const int wrp  = tid >> 5;
    const int lane = tid & 31;
    const int wm   = (wrp >> 2) * 64;
    const int wn   = (wrp & 3) * 32;
    const int bm   = blockIdx.y * 128;
    const int bn   = blockIdx.x * 128;

    const uint32_t as_base = smem_u32(As);
    const uint32_t bs_base = smem_u32(Bs);
    const uint32_t BUFS = (uint32_t)HG_BUF * 2u;

    const uint32_t a_row = (uint32_t)(wm + (lane & 15));
    const uint32_t a_col = (uint32_t)((lane >> 4) * 8);
    const uint32_t b_row = (uint32_t)(wn + ((lane >> 4) * 8) + (lane & 7));
    const uint32_t b_col = (uint32_t)(((lane >> 3) & 1) * 8);

    float acc[4][4][4] = {};

    const int g_row = tid >> 1;
    const int g_c   = (tid & 1) * 2;
    const uint32_t st_off = (uint32_t)(g_row * TSTR * 2) + (uint32_t)g_c * 16u;

    auto stage = [&](int nc, uint32_t boff) {
        const int seg = nc >> 5;
        const int kk  = (nc & 31) * BKC;
        const __nv_bfloat16* Ap = ((seg == 2) ? Alo : Ahi) + (size_t)(bm + g_row) * HH + kk;
        const __nv_bfloat16* Bp = ((seg == 1) ? Blo : Bhi) + (size_t)(bn + g_row) * HH + kk;
        cp_async16(as_base + boff + st_off,       Ap + g_c * 8);
        cp_async16(as_base + boff + st_off + 16u, Ap + g_c * 8 + 8);
        cp_async16(bs_base + boff + st_off,       Bp + g_c * 8);
        cp_async16(bs_base + boff + st_off + 16u, Bp + g_c * 8 + 8);
        cp_commit();
    };

    auto compute = [&](uint32_t boff) {
        #pragma unroll
        for (int ks = 0; ks < 2; ks++) {
            uint32_t a[4][4], b[2][4];
            #pragma unroll
            for (int mt = 0; mt < 4; mt++) {
                const uint32_t addr = as_base + boff +
                    ((a_row + mt * 16u) * TSTR + a_col + (uint32_t)ks * 16u) * 2u;
                ldm_x4(a[mt], addr);
            }
            #pragma unroll
            for (int np = 0; np < 2; np++) {
                const uint32_t addr = bs_base + boff +
                    ((b_row + np * 16u) * TSTR + b_col + (uint32_t)ks * 16u) * 2u;
                ldm_x4(b[np], addr);
            }
            #pragma unroll
            for (int mt = 0; mt < 4; mt++) {
                #pragma unroll
                for (int nt = 0; nt < 4; nt++) {
                    uint32_t bb[2] = { b[nt >> 1][(nt & 1) * 2],
                                       b[nt >> 1][(nt & 1) * 2 + 1] };
                    mma16816(acc[mt][nt], a[mt], bb);
                }
            }
        }
    };

    stage(0, 0u);
    stage(1, BUFS);

    #pragma unroll 1
    for (int c = 0; c < NCHK; c += 3) {
        cp_wait<1>();
        __syncthreads();
        stage(c + 2, 2u * BUFS);
        compute(0u);

        cp_wait<1>();
        __syncthreads();
        if (c + 3 < NCHK) stage(c + 3, 0u);
        compute(BUFS);

        if (c + 3 < NCHK) { cp_wait<1>(); } else { cp_wait<0>(); }
        __syncthreads();
        if (c + 4 < NCHK) stage(c + 4, BUFS);
        compute(2u * BUFS);
    }

    const int er = lane >> 2;
    const int ec = (lane & 3) * 2;
    #pragma unroll
    for (int mt = 0; mt < 4; mt++) {
        const int m0 = bm + wm + mt * 16 + er;
        #pragma unroll
        for (int nt = 0; nt < 4; nt++) {
            const int n0 = bn + wn + nt * 8 + ec;
            if (n0 + 1 < Nvalid) {
                const float bz0 = __ldg(&bias[n0]);
                const float bz1 = __ldg(&bias[n0 + 1]);
                *(float2*)&C[(size_t)m0 * ldc + n0] =
                    make_float2(acc[mt][nt][0] + bz0, acc[mt][nt][1] + bz1);
                *(float2*)&C[(size_t)(m0 + 8) * ldc + n0] =
                    make_float2(acc[mt][nt][2] + bz0, acc[mt][nt][3] + bz1);
            } else if (n0 < Nvalid) {
                const float bz0 = __ldg(&bias[n0]);
                C[(size_t)m0 * ldc + n0]       = acc[mt][nt][0] + bz0;
                C[(size_t)(m0 + 8) * ldc + n0] = acc[mt][nt][2] + bz0;
            }
        }
    }
}

// ---------------- fused dual-layer recurrence scan (R16) ---------------------
// Cross-layer software pipeline: phase p computes
//   h0(p+1) = tanh(Whh0 @ h0(p)            + pre0[p] + bhh0)      [p < SS]
//   h1(p)   = tanh(Wih1 @ h0(p) + Whh1 @ h1(p-1) + bias1c)        [p > 0]
// 129 phases, ONE grid barrier each. All 3 W tiles (hi/lo) SMEM-resident.
// G0(p) fragments are shared by the Whh0 and Wih1 products.
#define JT   16
#define WS   1032    // bf16 stride for W rows (%128 == 16 -> ldmatrix-clean)
#define FS_SMEM (size_t)((6*JT*WS) * 2 + 4*64*17*4)   // 215552 bytes

__global__ void __launch_bounds__(256, 1) rnn_fused_scan(
    const float* __restrict__ pre0,    // [SS][B][H]
    const float* __restrict__ Whh0,
    const float* __restrict__ Wih1,
    const float* __restrict__ Whh1,
    const float* __restrict__ bhh0,
    const float* __restrict__ bias1c,
    __nv_bfloat16* __restrict__ S0hi, __nv_bfloat16* __restrict__ S0lo,
    __nv_bfloat16* __restrict__ S1hi, __nv_bfloat16* __restrict__ S1lo,
    uint32_t* __restrict__ G0hi, uint32_t* __restrict__ G0lo,
    uint32_t* __restrict__ G1hi, uint32_t* __restrict__ G1lo)
{
    extern __shared__ __nv_bfloat16 smb[];
    __nv_bfloat16* W0h = smb;                    // [JT][WS] each
    __nv_bfloat16* W0l = W0h + JT * WS;
    __nv_bfloat16* Wi1h = W0l + JT * WS;
    __nv_bfloat16* Wi1l = Wi1h + JT * WS;
    __nv_bfloat16* Wh1h = Wi1l + JT * WS;
    __nv_bfloat16* Wh1l = Wh1h + JT * WS;
    float* Ds0 = (float*)(Wh1l + JT * WS);       // [2][64][17]
    float* Ds1 = Ds0 + 2 * 64 * 17;              // [2][64][17]

    const int tid  = threadIdx.x;
    const int wrp  = tid >> 5;
    const int lane = tid & 31;
    const int wg   = wrp >> 2;          // ks-half group (0/1)
    const int wl   = wrp & 3;           // b-group
    const int j0g  = blockIdx.x * JT;

    // one-time: three W tiles fp32 -> split bf16 in SMEM
    for (int idx = tid; idx < JT * 1024; idx += 256) {
        const int row = idx >> 10, col = idx & 1023;
        const size_t go = (size_t)(j0g + row) * HH + col;
        {
            const float v = Whh0[go];
            const __nv_bfloat16 h = __float2bfloat16(v);
            W0h[row * WS + col] = h;
            W0l[row * WS + col] = __float2bfloat16(v - __bfloat162float(h));
        }
        {
            const float v = Wih1[go];
            const __nv_bfloat16 h = __float2bfloat16(v);
            Wi1h[row * WS + col] = h;
            Wi1l[row * WS + col] = __float2bfloat16(v - __bfloat162float(h));
        }
        {
            const float v = Whh1[go];
            const __nv_bfloat16 h = __float2bfloat16(v);
            Wh1h[row * WS + col] = h;
            Wh1l[row * WS + col] = __float2bfloat16(v - __bfloat162float(h));
        }
    }
    const int eb = tid & 63, eq = tid >> 6;
    float b0reg[4], b1reg[4];
    #pragma unroll
    for (int i = 0; i < 4; i++) {
        b0reg[i] = bhh0[j0g + eq * 4 + i];
        b1reg[i] = bias1c[j0g + eq * 4 + i];
    }
    const int e_lane = (eb & 7) * 4 + (eq & 1) * 2;
    const int e_w    = 2 * ((eb & 15) >= 8 ? 1 : 0) + (eq >= 2 ? 1 : 0);
    const int e_off0 = (((int)blockIdx.x * 4 + (eb >> 4)) * 32 + e_lane) * 4 + e_w;
    __syncthreads();

    const uint32_t w0h_b = smem_u32(W0h), w0l_b = smem_u32(W0l);
    const uint32_t wi1h_b = smem_u32(Wi1h), wi1l_b = smem_u32(Wi1l);
    const uint32_t wh1h_b = smem_u32(Wh1h), wh1l_b = smem_u32(Wh1l);

    const uint32_t a_row = (uint32_t)(lane & 15);
    const uint32_t a_sel = (uint32_t)((lane >> 4) * 8);
    const int ks0 = wg * 32;
    const int gidx0 = wl * 32 + lane;

    const int er = lane >> 2, ec = (lane & 3) * 2;

    for (int p = 0; p <= SS; p++) {
        const bool do0 = (p < SS);
        const bool do1 = (p > 0);

        const uint4* g0h = (const uint4*)(G0hi + (size_t)p * GW);
        const uint4* g0l = (const uint4*)(G0lo + (size_t)p * GW);
        const size_t g1o = (size_t)(do1 ? p - 1 : 0) * GW;
        const uint4* g1h = (const uint4*)(G1hi + g1o);
        const uint4* g1l = (const uint4*)(G1lo + g1o);

        float acc0[3][2][4] = {};   // Whh0 @ G0(p)
        float acc1[3][2][4] = {};   // Wih1 @ G0(p) + Whh1 @ G1(p-1)

        uint4 p0h[4], p0l[4], p1h[4], p1l[4];
        #pragma unroll
        for (int q = 0; q < 3; q++) {
            const int gi = gidx0 + (ks0 + q) * 128;
            p0h[q] = g0h[gi];
            p0l[q] = g0l[gi];
            if (do1) { p1h[q] = g1h[gi]; p1l[q] = g1l[gi]; }
        }

        #pragma unroll 4
        for (int i = 0; i < 32; i++) {
            if (i + 3 < 32) {
                const int gi = gidx0 + (ks0 + i + 3) * 128;
                p0h[(i + 3) & 3] = g0h[gi];
                p0l[(i + 3) & 3] = g0l[gi];
                if (do1) { p1h[(i + 3) & 3] = g1h[gi]; p1l[(i + 3) & 3] = g1l[gi]; }
            }
            const int ks = ks0 + i;
            const uint32_t acol = ((a_row * WS) + (uint32_t)(ks * 16) + a_sel) * 2u;
            const int cur = i & 3;
            const uint32_t b0h4[4] = {p0h[cur].x, p0h[cur].y, p0h[cur].z, p0h[cur].w};
            const uint32_t b0l4[4] = {p0l[cur].x, p0l[cur].y, p0l[cur].z, p0l[cur].w};

            if (do0) {
                uint32_t ah[4], al[4];
                ldm_x4(ah, w0h_b + acol);
                ldm_x4(al, w0l_b + acol);
                #pragma unroll
                for (int nt = 0; nt < 2; nt++) {
                    const uint32_t bbh[2] = { b0h4[nt * 2], b0h4[nt * 2 + 1] };
                    const uint32_t bbl[2] = { b0l4[nt * 2], b0l4[nt * 2 + 1] };
                    mma16816(acc0[0][nt], ah, bbh);
                    mma16816(acc0[1][nt], ah, bbl);
                    mma16816(acc0[2][nt], al, bbh);
                }
            }
            if (do1) {
                uint32_t ih[4], il[4], hh[4], hl[4];
                ldm_x4(ih, wi1h_b + acol);
                ldm_x4(il, wi1l_b + acol);
                ldm_x4(hh, wh1h_b + acol);
                ldm_x4(hl, wh1l_b + acol);
                const uint32_t b1h4[4] = {p1h[cur].x, p1h[cur].y, p1h[cur].z, p1h[cur].w};
                const uint32_t b1l4[4] = {p1l[cur].x, p1l[cur].y, p1l[cur].z, p1l[cur].w};
                #pragma unroll
                for (int nt = 0; nt < 2; nt++) {
                    const uint32_t c0h[2] = { b0h4[nt * 2], b0h4[nt * 2 + 1] };
                    const uint32_t c0l[2] = { b0l4[nt * 2], b0l4[nt * 2 + 1] };
                    const uint32_t c1h[2] = { b1h4[nt * 2], b1h4[nt * 2 + 1] };
                    const uint32_t c1l[2] = { b1l4[nt * 2], b1l4[nt * 2 + 1] };
                    mma16816(acc1[0][nt], ih, c0h);
                    mma16816(acc1[1][nt], ih, c0l);
                    mma16816(acc1[2][nt], il, c0h);
                    mma16816(acc1[0][nt], hh, c1h);
                    mma16816(acc1[1][nt], hh, c1l);
                    mma16816(acc1[2][nt], hl, c1h);
                }
            }
        }

        // D frags -> SMEM [wg][b][j]
        {
            #pragma unroll
            for (int nt = 0; nt < 2; nt++) {
                const int bc = wl * 16 + nt * 8 + ec;
                if (do0) {
                    float* D = Ds0 + wg * 64 * 17;
                    D[bc * 17 + er]           = acc0[0][nt][0] + acc0[1][nt][0] + acc0[2][nt][0];
                    D[(bc + 1) * 17 + er]     = acc0[0][nt][1] + acc0[1][nt][1] + acc0[2][nt][1];
                    D[bc * 17 + er + 8]       = acc0[0][nt][2] + acc0[1][nt][2] + acc0[2][nt][2];
                    D[(bc + 1) * 17 + er + 8] = acc0[0][nt][3] + acc0[1][nt][3] + acc0[2][nt][3];
                }
                if (do1) {
                    float* D = Ds1 + wg * 64 * 17;
                    D[bc * 17 + er]           = acc1[0][nt][0] + acc1[1][nt][0] + acc1[2][nt][0];
                    D[(bc + 1) * 17 + er]     = acc1[0][nt][1] + acc1[1][nt][1] + acc1[2][nt][1];
                    D[bc * 17 + er + 8]       = acc1[0][nt][2] + acc1[1][nt][2] + acc1[2][nt][2];
                    D[(bc + 1) * 17 + er + 8] = acc1[0][nt][3] + acc1[1][nt][3] + acc1[2][nt][3];
                }
            }
        }
        __syncthreads();

        // epilogues
        if (do0) {
            const float* pp = pre0 + (size_t)p * BH + (size_t)eb * HH + j0g + eq * 4;
            const float4 pv4 = __ldg((const float4*)pp);
            const float pv[4] = {pv4.x, pv4.y, pv4.z, pv4.w};
            __nv_bfloat16 oh[4], ol[4];
            #pragma unroll
            for (int i = 0; i < 4; i++) {
                const int jj = eq * 4 + i;
                const float v = Ds0[eb * 17 + jj] + Ds0[64 * 17 + eb * 17 + jj]
                              + pv[i] + b0reg[i];
                const float th = tanhf(v);
                oh[i] = __float2bfloat16(th);
                ol[i] = __float2bfloat16(th - __bfloat162float(oh[i]));
            }
            const size_t o = (size_t)((p + 1) * 64 + eb) * HH + j0g + eq * 4;
            *(uint2*)(S0hi + o) = *(const uint2*)oh;
            *(uint2*)(S0lo + o) = *(const uint2*)ol;
            const size_t gb = (size_t)(p + 1) * GW;
            G0hi[gb + e_off0]     = *(const uint32_t*)&oh[0];
            G0hi[gb + e_off0 + 4] = *(const uint32_t*)&oh[2];
            G0lo[gb + e_off0]     = *(const uint32_t*)&ol[0];
            G0lo[gb + e_off0 + 4] = *(const uint32_t*)&ol[2];
        }
        if (do1) {
            __nv_bfloat16 oh[4], ol[4];
            #pragma unroll
            for (int i = 0; i < 4; i++) {
                const int jj = eq * 4 + i;
                const float v = Ds1[eb * 17 + jj] + Ds1[64 * 17 + eb * 17 + jj]
                              + b1reg[i];
                const float th = tanhf(v);
                oh[i] = __float2bfloat16(th);
                ol[i] = __float2bfloat16(th - __bfloat162float(oh[i]));
            }
            const size_t o = (size_t)(p * 64 + eb) * HH + j0g + eq * 4;
            *(uint2*)(S1hi + o) = *(const uint2*)oh;
            *(uint2*)(S1lo + o) = *(const uint2*)ol;
            const size_t gb = (size_t)p * GW;
            G1hi[gb + e_off0]     = *(const uint32_t*)&oh[0];
            G1hi[gb + e_off0 + 4] = *(const uint32_t*)&oh[2];
            G1lo[gb + e_off0]     = *(const uint32_t*)&ol[0];
            G1lo[gb + e_off0 + 4] = *(const uint32_t*)&ol[2];
        }

        grid_barrier((unsigned)p + 1u, GRIDB);
    }
}

// ---------------- tiny utility kernels ----------------
__global__ void init_kernel(const float* __restrict__ b_ih1,
                            const float* __restrict__ b_hh1)
{
    const int i = blockIdx.x * 256 + threadIdx.x;   // grid covers HH
    g_bias1c[i] = b_ih1[i] + b_hh1[i];
    if (i == 0) { g_arrive = 0u; g_release = 0u; }
}

__global__ void __launch_bounds__(256) final_kernel(float* __restrict__ outh)
{
    const int i = blockIdx.x * 256 + threadIdx.x;   // grid covers BH
    const size_t o = (size_t)(SS * 64) * HH + i;
    outh[i]      = __bfloat162float(g_S0hi[o]) + __bfloat162float(g_S0lo[o]);
    outh[BH + i] = __bfloat162float(g_S1hi[o]) + __bfloat162float(g_S1lo[o]);
}

// ---------------- launcher ----------------
extern "C" void kernel_launch(void* const* d_in, const int* in_sizes, int n_in,
                              void* d_out, int out_size)
{
    const int*   inputs = (const int*)  d_in[0];  // [S,B]
    const float* hidden = (const float*)d_in[1];  // [L,B,H]
    const float* emb    = (const float*)d_in[2];  // [V,E]
    const float* W_ih   = (const float*)d_in[3];  // [L,H,E]
    const float* b_ih   = (const float*)d_in[4];  // [L,H]
    const float* W_hh   = (const float*)d_in[5];  // [L,H,H]
    const float* b_hh   = (const float*)d_in[6];  // [L,H]
    const float* W_out  = (const float*)d_in[7];  // [V,H]
    const float* b_out  = (const float*)d_in[8];  // [V]

    const float* W_ih0 = W_ih;
    const float* W_ih1 = W_ih + (size_t)HH * HH;
    const float* W_hh0 = W_hh;
    const float* W_hh1 = W_hh + (size_t)HH * HH;
    const float* b_ih0 = b_ih;
    const float* b_ih1 = b_ih + HH;
    const float* b_hh0 = b_hh;
    const float* b_hh1 = b_hh + HH;

    float *pre0, *bias1c;
    __nv_bfloat16 *S0hi, *S0lo, *S1hi, *S1lo, *Ahi, *Alo, *Bhi, *Blo;
    uint32_t *G0hi, *G0lo, *G1hi, *G1lo;
    cudaGetSymbolAddress((void**)&pre0,   g_pre0);
    cudaGetSymbolAddress((void**)&bias1c, g_bias1c);
    cudaGetSymbolAddress((void**)&S0hi,   g_S0hi);
    cudaGetSymbolAddress((void**)&S0lo,   g_S0lo);
    cudaGetSymbolAddress((void**)&S1hi,   g_S1hi);
    cudaGetSymbolAddress((void**)&S1lo,   g_S1lo);
    cudaGetSymbolAddress((void**)&G0hi,   g_G0hi);
    cudaGetSymbolAddress((void**)&G0lo,   g_G0lo);
    cudaGetSymbolAddress((void**)&G1hi,   g_G1hi);
    cudaGetSymbolAddress((void**)&G1lo,   g_G1lo);
    cudaGetSymbolAddress((void**)&Ahi,    g_Ahi);
    cudaGetSymbolAddress((void**)&Alo,    g_Alo);
    cudaGetSymbolAddress((void**)&Bhi,    g_Bhi);
    cudaGetSymbolAddress((void**)&Blo,    g_Blo);

    float* out = (float*)d_out;
    const long long logitsN = (long long)MM * VV;
    float* outh = ((long long)out_size >= logitsN + 2LL * BH) ? out + logitsN : nullptr;

    cudaFuncSetAttribute(rnn_fused_scan, cudaFuncAttributeMaxDynamicSharedMemorySize,
                         (int)FS_SMEM);
    cudaFuncSetAttribute(hmma_gemm, cudaFuncAttributeMaxDynamicSharedMemorySize,
                         HG_SMEM);

    // bias1c + barrier reset (every replay)
    init_kernel<<<HH/256, 256>>>(b_ih1, b_hh1);
    // initial hidden -> G slabs t=0 (fragment layout, both layers)
    init_hid<<<(2*BH/4)/256, 256>>>(hidden);

    // Phase A: pre0 = (emb[tok]*32) @ W_ih0^T + b_ih0
    conv_gather<<<MM, 256>>>(inputs, emb, Ahi, Alo);
    conv_w<<<HH, 256>>>(W_ih0, HH, Bhi, Blo);
    {
        dim3 g(HH/128, MM/128);
        hmma_gemm<<<g, 256, HG_SMEM>>>(Ahi, Alo, Bhi, Blo, b_ih0, pre0, HH, HH);
    }

    // Fused dual-layer scan (replaces scan0 + pre1 GEMM + scan1)
    rnn_fused_scan<<<GRIDB, 256, FS_SMEM>>>(pre0, W_hh0, W_ih1, W_hh1,
                                            b_hh0, bias1c,
                                            S0hi, S0lo, S1hi, S1lo,
                                            G0hi, G0lo, G1hi, G1lo);

    // Phase C: logits = H1all @ W_out^T + b_out
    conv_w<<<NPAD, 256>>>(W_out, VV, Bhi, Blo);
    {
        dim3 g(NPAD/128, MM/128);
        hmma_gemm<<<g, 256, HG_SMEM>>>(S1hi + (size_t)64*HH, S1lo + (size_t)64*HH,
                                       Bhi, Blo, b_out, out, VV, VV);
    }

    // h_final = [h0(S-1), h1(S-1)]
    if (outh) final_kernel<<<BH/256, 256>>>(outh);
}

// round 17
// speedup vs baseline: 1.3468x; 1.3468x over previous
#include <cuda_runtime.h>
#include <cuda_bf16.h>
#include <math.h>
#include <stdint.h>

// Problem dims (fixed by the dataset)
#define SS 128      // sequence length
#define BB 64       // batch
#define HH 1024     // hidden = embedding dim
#define VV 10000    // vocab
#define MM (SS*BB)  // 8192 rows for the batched GEMMs
#define BH (BB*HH)  // 65536
#define GW (BH/2)   // uint32 words per timestep in the fragment slab
#define NPAD 10112  // vocab padded to the minimal 128-multiple >= VV (79 tiles)
#define GRIDB 64    // scan grid (64 j-tiles of 16)

// ---------------- device scratch (no allocations allowed) ----------------
__device__ __align__(16) float g_pre0[MM * HH];          // drive layer 0, [t][b][j]
__device__ __align__(16) float g_pre1[MM * HH];          // drive layer 1, [t][b][j]
__device__ __align__(16) __nv_bfloat16 g_S0hi[(SS+1) * BH];
__device__ __align__(16) __nv_bfloat16 g_S0lo[(SS+1) * BH];
__device__ __align__(16) __nv_bfloat16 g_S1hi[(SS+1) * BH];
__device__ __align__(16) __nv_bfloat16 g_S1lo[(SS+1) * BH];
// Fragment-layout hidden slabs (scan B operand); see R11 mapping comment.
__device__ __align__(16) uint32_t g_G0hi[(SS+1) * GW];
__device__ __align__(16) uint32_t g_G0lo[(SS+1) * GW];
__device__ __align__(16) uint32_t g_G1hi[(SS+1) * GW];
__device__ __align__(16) uint32_t g_G1lo[(SS+1) * GW];
__device__ __align__(16) __nv_bfloat16 g_Ahi[MM * HH];   // gathered emb (hi)
__device__ __align__(16) __nv_bfloat16 g_Alo[MM * HH];   // gathered emb (lo)
__device__ __align__(16) __nv_bfloat16 g_Bhi[NPAD * HH]; // weight operand (hi)
__device__ __align__(16) __nv_bfloat16 g_Blo[NPAD * HH]; // weight operand (lo)
__device__ __align__(16) float g_bias1c[HH];             // b_ih1 + b_hh1
__device__ unsigned g_arrive;                            // grid barrier: arrivals
__device__ unsigned g_release;                           // grid barrier: generation

// ---------------- generic helpers ----------------
__device__ __forceinline__ unsigned ldcg_u(const unsigned* p) {
    unsigned v; asm volatile("ld.global.cg.u32 %0, [%1];" : "=r"(v) : "l"(p)); return v;
}
__device__ __forceinline__ unsigned smem_u32(const void* p) {
    unsigned a;
    asm("{ .reg .u64 t; cvta.to.shared.u64 t, %1; cvt.u32.u64 %0, t; }" : "=r"(a) : "l"(p));
    return a;
}
__device__ __forceinline__ void cp_async16(unsigned dst, const void* src) {
    asm volatile("cp.async.cg.shared.global [%0], [%1], 16;" :: "r"(dst), "l"(src));
}
__device__ __forceinline__ void cp_commit() {
    asm volatile("cp.async.commit_group;");
}
template<int N>
__device__ __forceinline__ void cp_wait() {
    asm volatile("cp.async.wait_group %0;" :: "n"(N));
}

// grid barrier over NB resident blocks
__device__ __forceinline__ void grid_barrier(unsigned want, unsigned NB) {
    __syncthreads();
    if (threadIdx.x == 0) {
        __threadfence();
        unsigned prev = atomicAdd(&g_arrive, 1u);
        if (prev == want * NB - 1u) {
            atomicExch(&g_release, want);
        }
        while (ldcg_u(&g_release) < want) { __nanosleep(32); }
    }
    __syncthreads();
}

// ---------------- split-bf16 helpers ----------------
__device__ __forceinline__ uint32_t pack_bf2(float a, float b) {
    __nv_bfloat162 t2;
    t2.x = __float2bfloat16(a);
    t2.y = __float2bfloat16(b);
    return *(uint32_t*)&t2;
}
__device__ __forceinline__ void split4_store(float4 v,
    __nv_bfloat16* hi, __nv_bfloat16* lo, size_t off)
{
    float vv[4] = {v.x, v.y, v.z, v.w};
    uint32_t ph[2], pl[2];
    #pragma unroll
    for (int e = 0; e < 2; e++) {
        __nv_bfloat16 h0 = __float2bfloat16(vv[e*2+0]);
        __nv_bfloat16 h1 = __float2bfloat16(vv[e*2+1]);
        __nv_bfloat16 l0 = __float2bfloat16(vv[e*2+0] - __bfloat162float(h0));
        __nv_bfloat16 l1 = __float2bfloat16(vv[e*2+1] - __bfloat162float(h1));
        __nv_bfloat162 hh; hh.x = h0; hh.y = h1; ph[e] = *(uint32_t*)&hh;
        __nv_bfloat162 ll; ll.x = l0; ll.y = l1; pl[e] = *(uint32_t*)&ll;
    }
    *(uint2*)(hi + off) = make_uint2(ph[0], ph[1]);
    *(uint2*)(lo + off) = make_uint2(pl[0], pl[1]);
}

// weights [Nrows][K] -> hi/lo, zero-padded rows up to grid coverage
__global__ void __launch_bounds__(256) conv_w(
    const float* __restrict__ W, int Nrows,
    __nv_bfloat16* __restrict__ hi, __nv_bfloat16* __restrict__ lo)
{
    const int idx = blockIdx.x * 256 + threadIdx.x;
    const int row = idx >> 8;
    const int c4  = (idx & 255) * 4;
    float4 v = make_float4(0.f, 0.f, 0.f, 0.f);
    if (row < Nrows) v = *(const float4*)&W[(size_t)row * HH + c4];
    split4_store(v, hi, lo, (size_t)row * HH + c4);
}

// gathered, scaled embedding -> hi/lo A slab [m][K]
__global__ void __launch_bounds__(256) conv_gather(
    const int* __restrict__ gidx, const float* __restrict__ emb,
    __nv_bfloat16* __restrict__ hi, __nv_bfloat16* __restrict__ lo)
{
    const int idx = blockIdx.x * 256 + threadIdx.x;
    const int m  = idx >> 8;
    const int c4 = (idx & 255) * 4;
    float4 v = *(const float4*)&emb[(size_t)gidx[m] * HH + c4];
    v.x *= 32.f; v.y *= 32.f; v.z *= 32.f; v.w *= 32.f;
    split4_store(v, hi, lo, (size_t)m * HH + c4);
}

// initial hidden [l][b][k] fp32 -> G slabs t=0 (fragment layout, hi/lo)
__global__ void __launch_bounds__(256) init_hid(const float* __restrict__ hidden)
{
    const int i = blockIdx.x * 256 + threadIdx.x;   // grid covers 2*BH/4
    const int l = i >= (BH / 4);
    const int r = i - l * (BH / 4);
    const int b = r >> 8, c4 = (r & 255) * 4;       // 4 consecutive k's
    float4 v = *(const float4*)&hidden[(size_t)l * BH + (size_t)b * HH + c4];

    const uint32_t p0h = pack_bf2(v.x, v.y);
    const uint32_t p1h = pack_bf2(v.z, v.w);
    const float rx = v.x - __bfloat162float(__float2bfloat16(v.x));
    const float ry = v.y - __bfloat162float(__float2bfloat16(v.y));
    const float rz = v.z - __bfloat162float(__float2bfloat16(v.z));
    const float rw = v.w - __bfloat162float(__float2bfloat16(v.w));
    const uint32_t p0l = pack_bf2(rx, ry);
    const uint32_t p1l = pack_bf2(rz, rw);

    const int ks = c4 >> 4, k16 = c4 & 15;
    const int g = b >> 4, n16 = b & 15;
    const int w = 2 * (n16 >= 8 ? 1 : 0) + (k16 >= 8 ? 1 : 0);
    const int lane = (n16 & 7) * 4 + ((k16 & 7) >> 1);
    const int off0 = ((ks * 4 + g) * 32 + lane) * 4 + w;

    uint32_t* GH = l ? g_G1hi : g_G0hi;
    uint32_t* GL = l ? g_G1lo : g_G0lo;
    GH[off0] = p0h; GH[off0 + 4] = p1h;
    GL[off0] = p0l; GL[off0 + 4] = p1l;
}

// ---------------- mma.sync bf16 split GEMM (R13: 3-stage, occ=2 enforced) ----
#define BKC   32
#define TSTR  40
#define NCHK  96
#define HG_BUF   (128 * TSTR)                 // bf16 per stage per operand
#define HG_SMEM  (3 * HG_BUF * 2 * 2)         // 3 stages x 2 operands x 2B = 61440

__device__ __forceinline__ void ldm_x4(uint32_t* r, uint32_t addr) {
    asm volatile("ldmatrix.sync.aligned.m8n8.x4.shared.b16 {%0,%1,%2,%3}, [%4];"
                 : "=r"(r[0]), "=r"(r[1]), "=r"(r[2]), "=r"(r[3]) : "r"(addr));
}
__device__ __forceinline__ void mma16816(float* c, const uint32_t* a, const uint32_t* b) {
    asm volatile(
        "mma.sync.aligned.m16n8k16.row.col.f32.bf16.bf16.f32 "
        "{%0,%1,%2,%3}, {%4,%5,%6,%7}, {%8,%9}, {%0,%1,%2,%3};"
        : "+f"(c[0]), "+f"(c[1]), "+f"(c[2]), "+f"(c[3])
        : "r"(a[0]), "r"(a[1]), "r"(a[2]), "r"(a[3]), "r"(b[0]), "r"(b[1]));
}

__global__ void __launch_bounds__(256, 2) hmma_gemm(
    const __nv_bfloat16* __restrict__ Ahi, const __nv_bfloat16* __restrict__ Alo,
    const __nv_bfloat16* __restrict__ Bhi, const __nv_bfloat16* __restrict__ Blo,
    const float* __restrict__ bias, float* __restrict__ C, int ldc, int Nvalid)
{
    extern __shared__ __nv_bfloat16 hsm[];
    __nv_bfloat16* As = hsm;                 // [3][HG_BUF]
    __nv_bfloat16* Bs = hsm + 3 * HG_BUF;    // [3][HG_BUF]

    const int tid  = threadIdx.x;
    const int wrp  = tid >> 5;
    const int lane = tid & 31;
    const int wm   = (wrp >> 2) * 64;
    const int wn   = (wrp & 3) * 32;
    const int bm   = blockIdx.y * 128;
    const int bn   = blockIdx.x * 128;

    const uint32_t as_base = smem_u32(As);
    const uint32_t bs_base = smem_u32(Bs);
    const uint32_t BUFS = (uint32_t)HG_BUF * 2u;   // bytes per stage

    const uint32_t a_row = (uint32_t)(wm + (lane & 15));
    const uint32_t a_col = (uint32_t)((lane >> 4) * 8);
    const uint32_t b_row = (uint32_t)(wn + ((lane >> 4) * 8) + (lane & 7));
    const uint32_t b_col = (uint32_t)(((lane >> 3) & 1) * 8);

    float acc[4][4][4] = {};

    const int g_row = tid >> 1;
    const int g_c   = (tid & 1) * 2;
    const uint32_t st_off = (uint32_t)(g_row * TSTR * 2) + (uint32_t)g_c * 16u;

    auto stage = [&](int nc, uint32_t boff) {
        const int seg = nc >> 5;
        const int kk  = (nc & 31) * BKC;
        const __nv_bfloat16* Ap = ((seg == 2) ? Alo : Ahi) + (size_t)(bm + g_row) * HH + kk;
        const __nv_bfloat16* Bp = ((seg == 1) ? Blo : Bhi) + (size_t)(bn + g_row) * HH + kk;
        cp_async16(as_base + boff + st_off,       Ap + g_c * 8);
        cp_async16(as_base + boff + st_off + 16u, Ap + g_c * 8 + 8);
        cp_async16(bs_base + boff + st_off,       Bp + g_c * 8);
        cp_async16(bs_base + boff + st_off + 16u, Bp + g_c * 8 + 8);
        cp_commit();
    };

    auto compute = [&](uint32_t boff) {
        #pragma unroll
        for (int ks = 0; ks < 2; ks++) {
            uint32_t a[4][4], b[2][4];
            #pragma unroll
            for (int mt = 0; mt < 4; mt++) {
                const uint32_t addr = as_base + boff +
                    ((a_row + mt * 16u) * TSTR + a_col + (uint32_t)ks * 16u) * 2u;
                ldm_x4(a[mt], addr);
            }
            #pragma unroll
            for (int np = 0; np < 2; np++) {
                const uint32_t addr = bs_base + boff +
                    ((b_row + np * 16u) * TSTR + b_col + (uint32_t)ks * 16u) * 2u;
                ldm_x4(b[np], addr);
            }
            #pragma unroll
            for (int mt = 0; mt < 4; mt++) {
                #pragma unroll
                for (int nt = 0; nt < 4; nt++) {
                    uint32_t bb[2] = { b[nt >> 1][(nt & 1) * 2],
                                       b[nt >> 1][(nt & 1) * 2 + 1] };
                    mma16816(acc[mt][nt], a[mt], bb);
                }
            }
        }
    };

    // prologue: 2 chunks in flight
    stage(0, 0u);
    stage(1, BUFS);

    #pragma unroll 1
    for (int c = 0; c < NCHK; c += 3) {
        cp_wait<1>();
        __syncthreads();
        stage(c + 2, 2u * BUFS);
        compute(0u);

        cp_wait<1>();
        __syncthreads();
        if (c + 3 < NCHK) stage(c + 3, 0u);
        compute(BUFS);

        if (c + 3 < NCHK) { cp_wait<1>(); } else { cp_wait<0>(); }
        __syncthreads();
        if (c + 4 < NCHK) stage(c + 4, BUFS);
        compute(2u * BUFS);
    }

    const int er = lane >> 2;
    const int ec = (lane & 3) * 2;
    #pragma unroll
    for (int mt = 0; mt < 4; mt++) {
        const int m0 = bm + wm + mt * 16 + er;
        #pragma unroll
        for (int nt = 0; nt < 4; nt++) {
            const int n0 = bn + wn + nt * 8 + ec;
            if (n0 + 1 < Nvalid) {
                const float bz0 = __ldg(&bias[n0]);
                const float bz1 = __ldg(&bias[n0 + 1]);
                *(float2*)&C[(size_t)m0 * ldc + n0] =
                    make_float2(acc[mt][nt][0] + bz0, acc[mt][nt][1] + bz1);
                *(float2*)&C[(size_t)(m0 + 8) * ldc + n0] =
                    make_float2(acc[mt][nt][2] + bz0, acc[mt][nt][3] + bz1);
            } else if (n0 < Nvalid) {
                const float bz0 = __ldg(&bias[n0]);
                C[(size_t)m0 * ldc + n0]       = acc[mt][nt][0] + bz0;
                C[(size_t)(m0 + 8) * ldc + n0] = acc[mt][nt][2] + bz0;
            }
        }
    }
}

// ---------------- tensor-core recurrence scan (R11, unchanged) ---------------
#define JT   16
#define WS   1032    // bf16 stride for W rows (%128 == 16 -> ldmatrix-clean)
#define SCAN_SMEM (size_t)((2*JT*WS) * 2 + 2*64*17*4)

__global__ void __launch_bounds__(256, 1) rec_scan_mma(
    const float* __restrict__ pre,     // [SS][B][H]
    const float* __restrict__ W,       // [H][H] fp32 (row = out j)
    const float* __restrict__ bias,    // [H] or nullptr
    __nv_bfloat16* __restrict__ Shi,   // row-major slab hi [(SS+1)*64][H]
    __nv_bfloat16* __restrict__ Slo,   // row-major slab lo
    uint32_t* __restrict__ Ghi,        // fragment slab hi [(SS+1)*GW]
    uint32_t* __restrict__ Glo,        // fragment slab lo
    unsigned bar0)
{
    extern __shared__ __nv_bfloat16 smb[];
    __nv_bfloat16* Wh = smb;                   // [JT][WS]
    __nv_bfloat16* Wl = Wh + JT * WS;
    float* Ds = (float*)(Wl + JT * WS);        // [2][64][17]

    const int tid  = threadIdx.x;
    const int wrp  = tid >> 5;
    const int lane = tid & 31;
    const int wg   = wrp >> 2;
    const int wl   = wrp & 3;
    const int j0g  = blockIdx.x * JT;

    for (int idx = tid; idx < JT * 1024; idx += 256) {
        const int row = idx >> 10, col = idx & 1023;
        const float v = W[(size_t)(j0g + row) * HH + col];
        const __nv_bfloat16 h = __float2bfloat16(v);
        Wh[row * WS + col] = h;
        Wl[row * WS + col] = __float2bfloat16(v - __bfloat162float(h));
    }
    const int eb = tid & 63, eq = tid >> 6;
    float breg[4];
    #pragma unroll
    for (int i = 0; i < 4; i++)
        breg[i] = bias ? bias[j0g + eq * 4 + i] : 0.0f;
    const int e_lane = (eb & 7) * 4 + (eq & 1) * 2;
    const int e_w    = 2 * ((eb & 15) >= 8 ? 1 : 0) + (eq >= 2 ? 1 : 0);
    const int e_off0 = (((int)blockIdx.x * 4 + (eb >> 4)) * 32 + e_lane) * 4 + e_w;
    __syncthreads();

    const uint32_t wh_b = smem_u32(Wh), wl_b = smem_u32(Wl);

    const uint32_t a_row = (uint32_t)(lane & 15);
    const uint32_t a_sel = (uint32_t)((lane >> 4) * 8);
    const int ks0 = wg * 32;
    const int gidx0 = wl * 32 + lane;

    const int er = lane >> 2, ec = (lane & 3) * 2;

    for (int t = 0; t < SS; t++) {
        const uint4* gph = (const uint4*)(Ghi + (size_t)t * GW);
        const uint4* gpl = (const uint4*)(Glo + (size_t)t * GW);

        float acc[3][2][4] = {};
        uint4 pbh[4], pbl[4];

        #pragma unroll
        for (int p = 0; p < 3; p++) {
            pbh[p] = gph[gidx0 + (ks0 + p) * 128];
            pbl[p] = gpl[gidx0 + (ks0 + p) * 128];
        }

        #pragma unroll 4
        for (int i = 0; i < 32; i++) {
            if (i + 3 < 32) {
                pbh[(i + 3) & 3] = gph[gidx0 + (ks0 + i + 3) * 128];
                pbl[(i + 3) & 3] = gpl[gidx0 + (ks0 + i + 3) * 128];
            }
            const int ks = ks0 + i;
            uint32_t ah[4], al[4];
            const uint32_t acol = (uint32_t)(ks * 16) + a_sel;
            ldm_x4(ah, wh_b + (a_row * WS + acol) * 2u);
            ldm_x4(al, wl_b + (a_row * WS + acol) * 2u);

            const int cur = i & 3;
            const uint32_t bh4[4] = {pbh[cur].x, pbh[cur].y, pbh[cur].z, pbh[cur].w};
            const uint32_t bl4[4] = {pbl[cur].x, pbl[cur].y, pbl[cur].z, pbl[cur].w};
            #pragma unroll
            for (int nt = 0; nt < 2; nt++) {
                const uint32_t bbh[2] = { bh4[nt * 2], bh4[nt * 2 + 1] };
                const uint32_t bbl[2] = { bl4[nt * 2], bl4[nt * 2 + 1] };
                mma16816(acc[0][nt], ah, bbh);
                mma16816(acc[1][nt], ah, bbl);
                mma16816(acc[2][nt], al, bbh);
            }
        }

        {
            float* D = Ds + wg * 64 * 17;
            #pragma unroll
            for (int nt = 0; nt < 2; nt++) {
                const int bc = wl * 16 + nt * 8 + ec;
                D[bc * 17 + er]           = acc[0][nt][0] + acc[1][nt][0] + acc[2][nt][0];
                D[(bc + 1) * 17 + er]     = acc[0][nt][1] + acc[1][nt][1] + acc[2][nt][1];
                D[bc * 17 + er + 8]       = acc[0][nt][2] + acc[1][nt][2] + acc[2][nt][2];
                D[(bc + 1) * 17 + er + 8] = acc[0][nt][3] + acc[1][nt][3] + acc[2][nt][3];
            }
        }
        __syncthreads();

        {
            const float* pp = pre + (size_t)t * BH + (size_t)eb * HH + j0g + eq * 4;
            const float4 p0 = __ldg((const float4*)pp);
            const float pv[4] = {p0.x, p0.y, p0.z, p0.w};
            float th[4];
            __nv_bfloat16 oh[4], ol[4];
            #pragma unroll
            for (int i = 0; i < 4; i++) {
                const int jj = eq * 4 + i;
                const float v = Ds[eb * 17 + jj] + Ds[64 * 17 + eb * 17 + jj]
                              + pv[i] + breg[i];
                th[i] = tanhf(v);
                oh[i] = __float2bfloat16(th[i]);
                ol[i] = __float2bfloat16(th[i] - __bfloat162float(oh[i]));
            }
            const size_t o = (size_t)((t + 1) * 64 + eb) * HH + j0g + eq * 4;
            *(uint2*)(Shi + o) = *(const uint2*)oh;
            *(uint2*)(Slo + o) = *(const uint2*)ol;
            const size_t gb = (size_t)(t + 1) * GW;
            Ghi[gb + e_off0]     = *(const uint32_t*)&oh[0];
            Ghi[gb + e_off0 + 4] = *(const uint32_t*)&oh[2];
            Glo[gb + e_off0]     = *(const uint32_t*)&ol[0];
            Glo[gb + e_off0 + 4] = *(const uint32_t*)&ol[2];
        }

        grid_barrier(bar0 + (unsigned)t + 1u, GRIDB);
    }
}

// ---------------- tiny utility kernels ----------------
__global__ void init_kernel(const float* __restrict__ b_ih1,
                            const float* __restrict__ b_hh1)
{
    const int i = blockIdx.x * 256 + threadIdx.x;   // grid covers HH
    g_bias1c[i] = b_ih1[i] + b_hh1[i];
    if (i == 0) { g_arrive = 0u; g_release = 0u; }
}

__global__ void __launch_bounds__(256) final_kernel(float* __restrict__ outh)
{
    const int i = blockIdx.x * 256 + threadIdx.x;   // grid covers BH
    const size_t o = (size_t)(SS * 64) * HH + i;
    outh[i]      = __bfloat162float(g_S0hi[o]) + __bfloat162float(g_S0lo[o]);
    outh[BH + i] = __bfloat162float(g_S1hi[o]) + __bfloat162float(g_S1lo[o]);
}

// ---------------- launcher ----------------
extern "C" void kernel_launch(void* const* d_in, const int* in_sizes, int n_in,
                              void* d_out, int out_size)
{
    const int*   inputs = (const int*)  d_in[0];  // [S,B]
    const float* hidden = (const float*)d_in[1];  // [L,B,H]
    const float* emb    = (const float*)d_in[2];  // [V,E]
    const float* W_ih   = (const float*)d_in[3];  // [L,H,E]
    const float* b_ih   = (const float*)d_in[4];  // [L,H]
    const float* W_hh   = (const float*)d_in[5];  // [L,H,H]
    const float* b_hh   = (const float*)d_in[6];  // [L,H]
    const float* W_out  = (const float*)d_in[7];  // [V,H]
    const float* b_out  = (const float*)d_in[8];  // [V]

    const float* W_ih0 = W_ih;
    const float* W_ih1 = W_ih + (size_t)HH * HH;
    const float* W_hh0 = W_hh;
    const float* W_hh1 = W_hh + (size_t)HH * HH;
    const float* b_ih0 = b_ih;
    const float* b_ih1 = b_ih + HH;
    const float* b_hh0 = b_hh;
    const float* b_hh1 = b_hh + HH;

    float *pre0, *pre1, *bias1c;
    __nv_bfloat16 *S0hi, *S0lo, *S1hi, *S1lo, *Ahi, *Alo, *Bhi, *Blo;
    uint32_t *G0hi, *G0lo, *G1hi, *G1lo;
    cudaGetSymbolAddress((void**)&pre0,   g_pre0);
    cudaGetSymbolAddress((void**)&pre1,   g_pre1);
    cudaGetSymbolAddress((void**)&bias1c, g_bias1c);
    cudaGetSymbolAddress((void**)&S0hi,   g_S0hi);
    cudaGetSymbolAddress((void**)&S0lo,   g_S0lo);
    cudaGetSymbolAddress((void**)&S1hi,   g_S1hi);
    cudaGetSymbolAddress((void**)&S1lo,   g_S1lo);
    cudaGetSymbolAddress((void**)&G0hi,   g_G0hi);
    cudaGetSymbolAddress((void**)&G0lo,   g_G0lo);
    cudaGetSymbolAddress((void**)&G1hi,   g_G1hi);
    cudaGetSymbolAddress((void**)&G1lo,   g_G1lo);
    cudaGetSymbolAddress((void**)&Ahi,    g_Ahi);
    cudaGetSymbolAddress((void**)&Alo,    g_Alo);
    cudaGetSymbolAddress((void**)&Bhi,    g_Bhi);
    cudaGetSymbolAddress((void**)&Blo,    g_Blo);

    float* out = (float*)d_out;
    const long long logitsN = (long long)MM * VV;
    float* outh = ((long long)out_size >= logitsN + 2LL * BH) ? out + logitsN : nullptr;

    cudaFuncSetAttribute(rec_scan_mma, cudaFuncAttributeMaxDynamicSharedMemorySize,
                         (int)SCAN_SMEM);
    cudaFuncSetAttribute(hmma_gemm, cudaFuncAttributeMaxDynamicSharedMemorySize,
                         HG_SMEM);

    // bias1c + barrier reset (every replay)
    init_kernel<<<HH/256, 256>>>(b_ih1, b_hh1);
    // initial hidden -> G slabs t=0 (fragment layout, both layers)
    init_hid<<<(2*BH/4)/256, 256>>>(hidden);

    // Phase A: pre0 = (emb[tok]*32) @ W_ih0^T + b_ih0
    conv_gather<<<MM, 256>>>(inputs, emb, Ahi, Alo);
    conv_w<<<HH, 256>>>(W_ih0, HH, Bhi, Blo);
    {
        dim3 g(HH/128, MM/128);
        hmma_gemm<<<g, 256, HG_SMEM>>>(Ahi, Alo, Bhi, Blo, b_ih0, pre0, HH, HH);
    }

    // layer-0 scan
    rec_scan_mma<<<GRIDB, 256, SCAN_SMEM>>>(pre0, W_hh0, b_hh0,
                                            S0hi, S0lo, G0hi, G0lo, 0u);

    // pre1 = H0all @ W_ih1^T + (b_ih1 + b_hh1)
    conv_w<<<HH, 256>>>(W_ih1, HH, Bhi, Blo);
    {
        dim3 g(HH/128, MM/128);
        hmma_gemm<<<g, 256, HG_SMEM>>>(S0hi + (size_t)64*HH, S0lo + (size_t)64*HH,
                                       Bhi, Blo, bias1c, pre1, HH, HH);
    }

    // layer-1 scan (continues the monotonic barrier counter at SS)
    rec_scan_mma<<<GRIDB, 256, SCAN_SMEM>>>(pre1, W_hh1, nullptr,
                                            S1hi, S1lo, G1hi, G1lo, (unsigned)SS);

    // logits = H1all @ W_out^T + b_out
    conv_w<<<NPAD, 256>>>(W_out, VV, Bhi, Blo);
    {
        dim3 g(NPAD/128, MM/128);
        hmma_gemm<<<g, 256, HG_SMEM>>>(S1hi + (size_t)64*HH, S1lo + (size_t)64*HH,
                                       Bhi, Blo, b_out, out, VV, VV);
    }

    // h_final = [h0(S-1), h1(S-1)]
    if (outh) final_kernel<<<BH/256, 256>>>(outh);
}